// round 15
// baseline (speedup 1.0000x reference)
#include <cuda_runtime.h>
#include <cuda_bf16.h>

#define BB 64
#define LL 200
#define DD 128
#define MM 50
#define NQ 10000
#define CHK 8            // tokens per pipeline chunk
#define NCHK 25          // chunks per batch (200/8)
#define NPRE (BB * NCHK) // 1600 precompute blocks
#define NSCAN (BB * 2)   // 128 scan blocks
#define NFIN (BB * NCHK) // 1600 final blocks

// ---- device scratch ----
__device__ float  g_w[BB * LL * MM];
__device__ float  g_e[BB * LL * DD];
__device__ float  g_a[BB * LL * DD];
__device__ float  g_rp[BB * LL * DD];
__device__ float  g_fk[BB * LL * DD];
__device__ float4 g_We4[32 * DD];
__device__ float4 g_Wa4[32 * DD];
__device__ float4 g_Mk4[32 * 64];
__device__ float4 g_Wf4[64 * DD];
__device__ int    g_flag_pc[BB * NCHK];  // precompute (batch,chunk) done
__device__ int    g_prog[BB * 2];        // scan chunks done per (batch,dh)

__device__ __forceinline__ float2 ffma2(float2 a, float2 b, float2 c) {
    float2 d;
    asm("fma.rn.f32x2 %0, %1, %2, %3;"
        : "=l"(*reinterpret_cast<unsigned long long*>(&d))
        : "l"(*reinterpret_cast<unsigned long long*>(&a)),
          "l"(*reinterpret_cast<unsigned long long*>(&b)),
          "l"(*reinterpret_cast<unsigned long long*>(&c)));
    return d;
}
__device__ __forceinline__ float2 f2(float x, float y) { return make_float2(x, y); }

// ============================================================================
// Kernel T: weight transposes + pipeline flag reset
// ============================================================================
__global__ void transpose_kernel(const float* __restrict__ eW, const float* __restrict__ aW,
                                 const float* __restrict__ Mk, const float* __restrict__ fW)
{
    int i = blockIdx.x * 256 + threadIdx.x;
    if (i < BB * NCHK) g_flag_pc[i] = 0;
    if (i < BB * 2)    g_prog[i] = 0;
    if (i < 4096) {
        int d = i >> 5, j4 = i & 31;
        g_We4[j4 * 128 + d] = ((const float4*)eW)[d * 32 + j4];
        g_Wa4[j4 * 128 + d] = ((const float4*)aW)[d * 32 + j4];
    } else if (i < 6144) {
        int t = i - 4096;
        int m = t >> 5, j4 = t & 31;
        g_Mk4[j4 * 64 + m] = (m < MM) ? ((const float4*)Mk)[m * 32 + j4]
                                      : make_float4(0.f, 0.f, 0.f, 0.f);
    } else if (i < 14336) {
        int t = i - 6144;
        int d = t >> 6, j4 = t & 63;
        g_Wf4[j4 * 128 + d] = ((const float4*)fW)[d * 64 + j4];
    }
}

// ============================================================================
// Mega kernel: role-partitioned grid.
//   blocks [0, NPRE):            precompute, chunk-major (8 tokens each)
//   blocks [NPRE, NPRE+NSCAN):   scan (b x d-half), 160 threads active
//   blocks [NPRE+NSCAN, ...):    final (8 tokens each), chunk-major
// Scan spins on precompute chunk flags; final spins on scan progress.
// Waiters only depend on strictly earlier blockIdx -> FIFO dispatch => no
// deadlock. Cross-role data read via __ldcg; release = threadfence+atomic.
// ============================================================================
__global__ __launch_bounds__(256) void mega_kernel(
    const int* __restrict__ q, const int* __restrict__ r,
    const float* __restrict__ k_emb, const float* __restrict__ v_emb,
    const float* __restrict__ e_b, const float* __restrict__ a_b,
    const float* __restrict__ Mv0,
    const float* __restrict__ f_b, const float* __restrict__ p_W,
    const float* __restrict__ p_b,
    float* __restrict__ mv_out, float* __restrict__ p_out, int write_mv)
{
    int bid = blockIdx.x;
    int tid = threadIdx.x;

    if (bid < NPRE) {
        // ================= PRECOMPUTE ROLE =================
        __shared__ float k_s[CHK * DD];
        __shared__ float v_s[CHK * DD];
        __shared__ float lg_s[CHK * 52];
        __shared__ int qs[CHK], xs[CHK];

        int chunk = bid >> 6;        // chunk-major
        int batch = bid & 63;
        int bl0 = batch * LL + chunk * CHK;

        if (tid < CHK) {
            int qi = q[bl0 + tid];
            qs[tid] = qi;
            xs[tid] = qi + NQ * r[bl0 + tid];
        }
        __syncthreads();

        float4* k4 = (float4*)k_s;
        float4* v4 = (float4*)v_s;
        const float4* ke4 = (const float4*)k_emb;
        const float4* ve4 = (const float4*)v_emb;
        {   // exactly one iteration per thread (CHK*32 == 256)
            int tok = tid >> 5, j = tid & 31;
            k4[tid] = ke4[qs[tok] * 32 + j];
            v4[tid] = ve4[xs[tok] * 32 + j];
        }
        __syncthreads();

        // logits: (m 0..63) x (4 tg of 2 tokens)
        {
            int m = tid & 63, tg = tid >> 6;
            float2 a0 = f2(0, 0), a1 = f2(0, 0);
            #pragma unroll 4
            for (int j4 = 0; j4 < 32; j4++) {
                float4 mk = g_Mk4[j4 * 64 + m];
                float2 mlo = f2(mk.x, mk.y), mhi = f2(mk.z, mk.w);
                float4 c0 = k4[(tg * 2 + 0) * 32 + j4];
                float4 c1 = k4[(tg * 2 + 1) * 32 + j4];
                a0 = ffma2(mlo, f2(c0.x, c0.y), a0); a0 = ffma2(mhi, f2(c0.z, c0.w), a0);
                a1 = ffma2(mlo, f2(c1.x, c1.y), a1); a1 = ffma2(mhi, f2(c1.z, c1.w), a1);
            }
            if (m < MM) {
                lg_s[(tg * 2 + 0) * 52 + m] = a0.x + a0.y;
                lg_s[(tg * 2 + 1) * 52 + m] = a1.x + a1.y;
            }
        }
        __syncthreads();

        // softmax: 8 warps x 1 token
        {
            int wid = tid >> 5, lane = tid & 31;
            if (wid < CHK) {
                int tok = wid;
                float v0 = lg_s[tok * 52 + lane];
                float v1 = (lane < MM - 32) ? lg_s[tok * 52 + 32 + lane] : -1e30f;
                float mx = fmaxf(v0, v1);
                #pragma unroll
                for (int o = 16; o; o >>= 1) mx = fmaxf(mx, __shfl_xor_sync(0xFFFFFFFFu, mx, o));
                float e0 = expf(v0 - mx);
                float e1 = (lane < MM - 32) ? expf(v1 - mx) : 0.f;
                float s = e0 + e1;
                #pragma unroll
                for (int o = 16; o; o >>= 1) s += __shfl_xor_sync(0xFFFFFFFFu, s, o);
                float inv = 1.f / s;
                int g = bl0 + tok;
                g_w[g * MM + lane] = e0 * inv;
                if (lane < MM - 32) g_w[g * MM + 32 + lane] = e1 * inv;
            }
        }

        // e/a GEMV: (d 0..127) x (2 tg of 4 tokens)
        int d = tid & 127, tg = tid >> 7;
        {
            float2 ae[4], aa[4];
            #pragma unroll
            for (int t = 0; t < 4; t++) { ae[t] = f2(0, 0); aa[t] = f2(0, 0); }
            #pragma unroll 4
            for (int j4 = 0; j4 < 32; j4++) {
                float4 we = g_We4[j4 * 128 + d];
                float4 wa = g_Wa4[j4 * 128 + d];
                float2 welo = f2(we.x, we.y), wehi = f2(we.z, we.w);
                float2 walo = f2(wa.x, wa.y), wahi = f2(wa.z, wa.w);
                #pragma unroll
                for (int t = 0; t < 4; t++) {
                    float4 v = v4[(tg * 4 + t) * 32 + j4];
                    float2 vlo = f2(v.x, v.y), vhi = f2(v.z, v.w);
                    ae[t] = ffma2(welo, vlo, ae[t]); ae[t] = ffma2(wehi, vhi, ae[t]);
                    aa[t] = ffma2(walo, vlo, aa[t]); aa[t] = ffma2(wahi, vhi, aa[t]);
                }
            }
            float eb = e_b[d], ab = a_b[d];
            #pragma unroll
            for (int t = 0; t < 4; t++) {
                int g = bl0 + tg * 4 + t;
                g_e[g * DD + d] = 1.f / (1.f + expf(-(ae[t].x + ae[t].y + eb)));
                g_a[g * DD + d] = tanhf(aa[t].x + aa[t].y + ab);
            }
        }

        // fk GEMV (k-half of f)
        {
            float2 fk[4];
            #pragma unroll
            for (int t = 0; t < 4; t++) fk[t] = f2(0, 0);
            #pragma unroll 4
            for (int j4 = 0; j4 < 32; j4++) {
                float4 w = g_Wf4[(32 + j4) * 128 + d];
                float2 wlo = f2(w.x, w.y), whi = f2(w.z, w.w);
                #pragma unroll
                for (int t = 0; t < 4; t++) {
                    float4 c = k4[(tg * 4 + t) * 32 + j4];
                    fk[t] = ffma2(wlo, f2(c.x, c.y), fk[t]);
                    fk[t] = ffma2(whi, f2(c.z, c.w), fk[t]);
                }
            }
            #pragma unroll
            for (int t = 0; t < 4; t++)
                g_fk[(bl0 + tg * 4 + t) * DD + d] = fk[t].x + fk[t].y;
        }

        // release this chunk
        __threadfence();
        __syncthreads();
        if (tid == 0) atomicExch(&g_flag_pc[batch * NCHK + chunk], 1);

    } else if (bid < NPRE + NSCAN) {
        // ================= SCAN ROLE (160 threads) =================
        __shared__ float4 sm_rp[2][10][16];

        if (tid >= 160) return;
        int s  = bid - NPRE;
        int b  = s >> 1;
        int dh = s & 1;
        int l16 = tid & 15;
        int mg  = tid >> 4;
        int m0  = mg * 5;
        int d   = dh * 64 + l16 * 4;

        const float4* Mv04 = (const float4*)Mv0;
        float2 Slo[5], Shi[5];
        #pragma unroll
        for (int i = 0; i < 5; i++) {
            float4 sv = Mv04[((m0 + i) * DD + d) >> 2];
            Slo[i] = f2(sv.x, sv.y);
            Shi[i] = f2(sv.z, sv.w);
        }

        float4* out4 = (float4*)mv_out;
        long base201 = (long)b * 201 * (MM * DD);
        if (write_mv) {
            #pragma unroll
            for (int i = 0; i < 5; i++)
                __stcs(&out4[(base201 + (m0 + i) * DD + d) >> 2],
                       make_float4(Slo[i].x, Slo[i].y, Shi[i].x, Shi[i].y));
        }

        const float4* e4p = (const float4*)g_e;
        const float4* a4p = (const float4*)g_a;
        int  wbase  = (b * LL) * MM + m0;
        int  eabase = ((b * LL) * DD + d) >> 2;
        long obase  = base201 + MM * DD;
        int  rpbase = (b * LL) * DD + dh * 64;

        // wait for chunks 0 and 1 (prefetch crosses a chunk boundary)
        if (tid == 0) {
            while (atomicAdd(&g_flag_pc[b * NCHK + 0], 0) == 0) __nanosleep(64);
            while (atomicAdd(&g_flag_pc[b * NCHK + 1], 0) == 0) __nanosleep(64);
        }
        asm volatile("bar.sync 1, 160;" ::: "memory");

        float wv[5];
        #pragma unroll
        for (int i = 0; i < 5; i++) wv[i] = __ldcg(&g_w[wbase + i]);
        float4 ecur = __ldcg(&e4p[eabase]);
        float4 acur = __ldcg(&a4p[eabase]);

        for (int c = 0; c < NCHK; c++) {
            for (int tl = 0; tl < CHK; tl++) {
                int t = c * CHK + tl;
                int tn = (t + 1 < LL) ? t + 1 : t;
                float wn[5];
                #pragma unroll
                for (int i = 0; i < 5; i++) wn[i] = __ldcg(&g_w[wbase + tn * MM + i]);
                float4 en = __ldcg(&e4p[eabase + tn * 32]);
                float4 an = __ldcg(&a4p[eabase + tn * 32]);

                float2 nelo = f2(-ecur.x, -ecur.y), nehi = f2(-ecur.z, -ecur.w);
                float2 alo  = f2(acur.x, acur.y),   ahi  = f2(acur.z, acur.w);
                float2 rlo  = f2(0.f, 0.f),         rhi  = f2(0.f, 0.f);

                long ob = obase + (long)t * (MM * DD);
                #pragma unroll
                for (int i = 0; i < 5; i++) {
                    float2 w2 = f2(wv[i], wv[i]);
                    rlo = ffma2(w2, Slo[i], rlo);
                    rhi = ffma2(w2, Shi[i], rhi);
                    float2 tlo = ffma2(nelo, Slo[i], alo);
                    float2 thi = ffma2(nehi, Shi[i], ahi);
                    Slo[i] = ffma2(w2, tlo, Slo[i]);
                    Shi[i] = ffma2(w2, thi, Shi[i]);
                    if (write_mv)
                        __stcs(&out4[(ob + (m0 + i) * DD + d) >> 2],
                               make_float4(Slo[i].x, Slo[i].y, Shi[i].x, Shi[i].y));
                }

                sm_rp[t & 1][mg][l16] = make_float4(rlo.x, rlo.y, rhi.x, rhi.y);
                asm volatile("bar.sync 1, 160;" ::: "memory");
                if (tid < 64) {
                    const float* sp = (const float*)sm_rp[t & 1];
                    float sum = 0.f;
                    #pragma unroll
                    for (int g = 0; g < 10; g++) sum += sp[g * 64 + tid];
                    g_rp[rpbase + t * DD + tid] = sum;
                }
                // sm_rp[t&1] rewritten at t+2, after the t+1 barrier -> safe
                #pragma unroll
                for (int i = 0; i < 5; i++) wv[i] = wn[i];
                ecur = en;
                acur = an;
            }
            // chunk done: release rp progress, pre-wait next-next chunk flag
            if (tid < 64) __threadfence();
            asm volatile("bar.sync 1, 160;" ::: "memory");
            if (tid == 0) {
                atomicAdd(&g_prog[b * 2 + dh], 1);
                int nx = c + 2;
                if (nx < NCHK)
                    while (atomicAdd(&g_flag_pc[b * NCHK + nx], 0) == 0) __nanosleep(64);
            }
            asm volatile("bar.sync 1, 160;" ::: "memory");
        }

    } else {
        // ================= FINAL ROLE =================
        __shared__ float cat_s[CHK * DD];   // rp stage (4KB), reused for f

        int fidx  = bid - (NPRE + NSCAN);
        int chunk = fidx >> 6;       // chunk-major
        int batch = fidx & 63;
        int bl0 = batch * LL + chunk * CHK;

        if (tid == 0) {
            int tgt = chunk + 1;
            while (atomicAdd(&g_prog[batch * 2 + 0], 0) < tgt) __nanosleep(64);
            while (atomicAdd(&g_prog[batch * 2 + 1], 0) < tgt) __nanosleep(64);
        }
        __syncthreads();

        float4* cat4 = (float4*)cat_s;
        const float4* rp4 = (const float4*)g_rp;
        cat4[tid] = __ldcg(&rp4[bl0 * 32 + tid]);   // CHK*32 == 256
        __syncthreads();

        int d = tid & 127, tg = tid >> 7;
        float2 acc[4];
        float fkv[4];
        #pragma unroll
        for (int t = 0; t < 4; t++) {
            acc[t] = f2(0, 0);
            fkv[t] = __ldcg(&g_fk[(bl0 + tg * 4 + t) * DD + d]);
        }
        #pragma unroll 8
        for (int j4 = 0; j4 < 32; j4++) {
            float4 w = g_Wf4[j4 * 128 + d];
            float2 wlo = f2(w.x, w.y), whi = f2(w.z, w.w);
            #pragma unroll
            for (int t = 0; t < 4; t++) {
                float4 c = cat4[(tg * 4 + t) * 32 + j4];
                acc[t] = ffma2(wlo, f2(c.x, c.y), acc[t]);
                acc[t] = ffma2(whi, f2(c.z, c.w), acc[t]);
            }
        }
        float fb = f_b[d], pw = p_W[d];
        __syncthreads();
        #pragma unroll
        for (int t = 0; t < 4; t++)
            cat_s[(tg * 4 + t) * 128 + d] =
                tanhf(acc[t].x + acc[t].y + fkv[t] + fb) * pw;
        __syncthreads();

        {
            int wid = tid >> 5, lane = tid & 31;
            float pb = p_b[0];
            float sum = cat_s[wid * 128 + lane] + cat_s[wid * 128 + lane + 32]
                      + cat_s[wid * 128 + lane + 64] + cat_s[wid * 128 + lane + 96];
            #pragma unroll
            for (int o = 16; o; o >>= 1) sum += __shfl_xor_sync(0xFFFFFFFFu, sum, o);
            if (lane == 0) p_out[bl0 + wid] = 1.f / (1.f + expf(-(sum + pb)));
        }
    }
}

// ============================================================================
extern "C" void kernel_launch(void* const* d_in, const int* in_sizes, int n_in,
                              void* d_out, int out_size)
{
    const int*   q     = (const int*)  d_in[0];
    const int*   r     = (const int*)  d_in[1];
    const float* k_emb = (const float*)d_in[2];
    const float* v_emb = (const float*)d_in[3];
    const float* Mk    = (const float*)d_in[4];
    const float* Mv0   = (const float*)d_in[5];
    const float* f_W   = (const float*)d_in[6];
    const float* f_b   = (const float*)d_in[7];
    const float* p_W   = (const float*)d_in[8];
    const float* p_b   = (const float*)d_in[9];
    const float* e_W   = (const float*)d_in[10];
    const float* e_b   = (const float*)d_in[11];
    const float* a_W   = (const float*)d_in[12];
    const float* a_b   = (const float*)d_in[13];

    float* out = (float*)d_out;
    const int  P_CNT  = BB * LL;                     // 12800
    const long MV_CNT = (long)BB * 201 * MM * DD;    // 82,329,600

    float* p_out  = out;
    float* mv_out = out;
    int write_mv  = 0;
    if ((long)out_size >= (long)P_CNT + MV_CNT) {
        mv_out = out + P_CNT;
        write_mv = 1;
    }

    transpose_kernel<<<56, 256>>>(e_W, a_W, Mk, f_W);
    mega_kernel<<<NPRE + NSCAN + NFIN, 256>>>(
        q, r, k_emb, v_emb, e_b, a_b, Mv0, f_b, p_W, p_b,
        mv_out, p_out, write_mv);
}